// round 16
// baseline (speedup 1.0000x reference)
#include <cuda_runtime.h>
#include <cuda_fp16.h>
#include <cstdint>
#include <cstddef>

#define SEQ 2048
#define BZ 16
#define DIM 1024
#define MROWS (SEQ*BZ)
#define KC 32
#define NKC 32
#define TILEA 8192            // 128 rows x 32 cols fp16
#define SMEM_G (3*2*TILEA)    // 48 KB

__device__ __align__(256) __half g_Xh[(size_t)MROWS*DIM];           // fp16(x), [b][s][d]
__device__ __align__(256) __half g_Wt[(size_t)16*DIM*DIM];          // fp16(W[l]^T) : [l][e'][e]
__device__ __align__(256) __half g_Wbt[(size_t)DIM*DIM];            // fp16(W_base^T) : [d][e]
__device__ __align__(256) __half g_Bc[(size_t)16*DIM*DIM];          // fp16(Bt[l][e'][d])
__device__ __align__(256) float g_bc[16*DIM];

__device__ __forceinline__ uint32_t smem_u32(const void* p){
    uint32_t a;
    asm("{ .reg .u64 t; cvta.to.shared.u64 t, %1; cvt.u32.u64 %0, t; }" : "=r"(a) : "l"(p));
    return a;
}
#define SWZ64(o) ((o) ^ (((o) >> 3) & 0x30))

__device__ __forceinline__ void cp_async16(uint32_t s, const void* g){
    asm volatile("cp.async.cg.shared.global [%0], [%1], 16;" :: "r"(s), "l"(g));
}
#define CP_COMMIT() asm volatile("cp.async.commit_group;" ::: "memory")
#define CP_WAIT1()  asm volatile("cp.async.wait_group 1;" ::: "memory")
#define CP_WAIT0()  asm volatile("cp.async.wait_group 0;" ::: "memory")

__device__ __forceinline__ void ldsm4(uint32_t* r, uint32_t addr){
    asm volatile("ldmatrix.sync.aligned.m8n8.x4.shared.b16 {%0,%1,%2,%3}, [%4];"
        : "=r"(r[0]), "=r"(r[1]), "=r"(r[2]), "=r"(r[3]) : "r"(addr));
}
__device__ __forceinline__ void mma16816h(float* d, const uint32_t* a, const uint32_t* b){
    asm volatile("mma.sync.aligned.m16n8k16.row.col.f32.f16.f16.f32 "
        "{%0,%1,%2,%3}, {%4,%5,%6,%7}, {%8,%9}, {%0,%1,%2,%3};"
        : "+f"(d[0]), "+f"(d[1]), "+f"(d[2]), "+f"(d[3])
        : "r"(a[0]), "r"(a[1]), "r"(a[2]), "r"(a[3]), "r"(b[0]), "r"(b[1]));
}

__device__ __forceinline__ bool lang_used(int l, const int* lang_ids, const int* dict_len, int has_dict){
    int dl = has_dict ? dict_len[0] : 32000;
    bool u = false;
#pragma unroll
    for (int i = 0; i < BZ; i++) u |= ((dl - 1 - lang_ids[i]) == l);
    return u;
}

// ---------------- prologue kernels ----------------
// x[s][b][d] fp32 -> Xh[b][s][d] fp16 (batch-major so gemm1 A tiles are contiguous)
__global__ void split_x_kernel(const float* __restrict__ in){
    size_t i = (size_t)blockIdx.x * 256 + threadIdx.x;   // i indexes float4 groups
    float4 v = reinterpret_cast<const float4*>(in)[i];
    uint32_t h[4];
    float f[4] = {v.x, v.y, v.z, v.w};
#pragma unroll
    for (int k = 0; k < 4; k++)
        h[k] = (uint32_t)__half_as_ushort(__float2half_rn(f[k]));
    uint2 ph; ph.x = h[0] | (h[1] << 16); ph.y = h[2] | (h[3] << 16);
    size_t row = i >> 8;                 // (s*BZ + b), 256 float4 per row
    size_t s = row >> 4, b = row & 15;
    size_t drow = (b << 11) + s;         // b*SEQ + s
    reinterpret_cast<uint2*>(g_Xh)[(drow << 8) + (i & 255)] = ph;
}
// Merged transpose: planes 0..15 transpose W[l] -> g_Wt[l] (lang-skipped);
// plane 16 transposes W_base -> g_Wbt.
__global__ void transpose_half_kernel(const float* __restrict__ W,
                                      const float* __restrict__ W_base,
                                      const int* __restrict__ lang_ids,
                                      const int* __restrict__ dict_len,
                                      int has_dict){
    int l = blockIdx.z;
    const float* src;
    __half* dst;
    if (l < 16){
        if (!lang_used(l, lang_ids, dict_len, has_dict)) return;
        src = W + ((size_t)l << 20);
        dst = g_Wt + ((size_t)l << 20);
    } else {
        src = W_base;
        dst = g_Wbt;
    }
    __shared__ float t[32][33];
    int r0 = blockIdx.x * 32;
    int c0 = blockIdx.y * 32;
    int tx = threadIdx.x, ty = threadIdx.y;
#pragma unroll
    for (int j = 0; j < 32; j += 8)
        t[ty + j][tx] = src[(size_t)(r0 + ty + j) * DIM + c0 + tx];
    __syncthreads();
#pragma unroll
    for (int j = 0; j < 32; j += 8){
        float v = t[tx][ty + j];
        dst[(size_t)(c0 + ty + j) * DIM + r0 + tx] = __float2half_rn(v);
    }
}
// bc[l][e'] = bias[l][e'] + sum_e b_base[e] * W[l][e][e']   (parallel e-reduction)
__global__ void __launch_bounds__(1024,1) bc_kernel(
    const float* __restrict__ W, const float* __restrict__ b_base,
    const float* __restrict__ bias,
    const int* __restrict__ lang_ids, const int* __restrict__ dict_len, int has_dict){
    int l = blockIdx.x;
    if (!lang_used(l, lang_ids, dict_len, has_dict)) return;
    __shared__ float red[1024];
    int t  = threadIdx.x & 127;
    int es = threadIdx.x >> 7;
    int e2 = blockIdx.y * 128 + t;
    const float* Wl = W + ((size_t)l << 20);
    float s = 0.f;
#pragma unroll 8
    for (int e = es*128; e < es*128 + 128; e++)
        s += b_base[e] * Wl[(size_t)e * DIM + e2];
    red[threadIdx.x] = s;
    __syncthreads();
#pragma unroll
    for (int st = 512; st >= 128; st >>= 1){
        if (threadIdx.x < st) red[threadIdx.x] += red[threadIdx.x + st];
        __syncthreads();
    }
    if (threadIdx.x < 128)
        g_bc[l * DIM + e2] = red[threadIdx.x] + bias[(size_t)l * DIM + e2];
}

// ---------------- GEMM via mma.sync fp16, fully 1-pass (R8 config) ----------------
// CTA tile 128x128, warp tile 64x64 (2x2), K-chunk 32, SW64, 3 stages, 128 threads, 2 CTA/SM.
// MODE 0: Bt[l] = Wt[l] @ Wbt^T -> g_Bc fp16 (skips unused l)
// MODE 1: out[s][bb][e'] = Xh[bb][s][:] @ Bt[id]^T + bc[id]
template<int MODE>
__global__ void __launch_bounds__(128,2) gemm_kernel(
    const __half* __restrict__ A0, const __half* __restrict__ B0,
    const float* __restrict__ addvec,
    const int* __restrict__ lang_ids, const int* __restrict__ dict_len, int has_dict,
    float* __restrict__ out)
{
    extern __shared__ char smem_raw[];
    uint32_t tiles = smem_u32(smem_raw);
    int tid = threadIdx.x, wid = tid >> 5, lid = tid & 31;
    int wm = wid & 1, wn = wid >> 1;
    int nt = blockIdx.x, mt = blockIdx.y, zb = blockIdx.z;

    const __half *Asrc, *Bsrc;
    int id = 0;
    if (MODE == 0){
        if (!lang_used(zb, lang_ids, dict_len, has_dict)) return;
        Asrc = A0 + ((size_t)zb << 20) + (size_t)mt*128*DIM;
        Bsrc = B0 + (size_t)nt*128*DIM;
    } else {
        int dl = has_dict ? dict_len[0] : 32000;
        id = dl - 1 - lang_ids[zb];
        Asrc = A0 + ((size_t)zb*SEQ + (size_t)mt*128)*DIM;     // [b][s][d] contiguous
        Bsrc = B0 + ((size_t)id << 20) + (size_t)nt*128*DIM;
    }

    auto load_stage = [&](int kc, int st){
        uint32_t sb = tiles + st * (2*TILEA);
        const char* gA = (const char*)Asrc + (size_t)kc * (KC*2);
        const char* gB = (const char*)Bsrc + (size_t)kc * (KC*2);
#pragma unroll
        for (int i = 0; i < 4; i++){
            int idx = tid + 128 * i;
            int row = idx >> 2, seg = idx & 3;
            uint32_t so = SWZ64(row*64 + seg*16);
            cp_async16(sb + so, gA + (size_t)row*2048 + seg*16);
            cp_async16(sb + TILEA + so, gB + (size_t)row*2048 + seg*16);
        }
        CP_COMMIT();
    };

    float acc[4][8][4];
#pragma unroll
    for (int a = 0; a < 4; a++)
#pragma unroll
        for (int b = 0; b < 8; b++)
#pragma unroll
            for (int c = 0; c < 4; c++) acc[a][b][c] = 0.f;

    int a_row = wm*64 + (lid & 7) + ((lid >> 3) & 1) * 8;
    int a_sg  = (lid >> 4);
    int b_row = wn*64 + (lid & 7) + (lid >> 4) * 8;
    int b_sg  = (lid >> 3) & 1;

    load_stage(0, 0); load_stage(1, 1);

    for (int kc = 0; kc < NKC; kc++){
        int st = kc % 3;
        if (kc == NKC-1) { CP_WAIT0(); } else { CP_WAIT1(); }
        __syncthreads();
        if (kc + 2 < NKC) load_stage(kc + 2, (kc + 2) % 3);

        uint32_t sb = tiles + st * (2*TILEA);
        uint32_t sA = sb, sB = sb + TILEA;
#pragma unroll
        for (int ks = 0; ks < 2; ks++){
            uint32_t ah[4][4], bh[4][4];
#pragma unroll
            for (int mi = 0; mi < 4; mi++){
                uint32_t off = SWZ64((a_row + mi*16)*64 + (ks*2 + a_sg)*16);
                ldsm4(ah[mi], sA + off);
            }
#pragma unroll
            for (int ni2 = 0; ni2 < 4; ni2++){
                uint32_t off = SWZ64((b_row + ni2*16)*64 + (ks*2 + b_sg)*16);
                ldsm4(bh[ni2], sB + off);
            }
#pragma unroll
            for (int mi = 0; mi < 4; mi++)
#pragma unroll
                for (int ni = 0; ni < 8; ni++)
                    mma16816h(acc[mi][ni], ah[mi], &bh[ni>>1][(ni&1)*2]);
        }
    }

    // epilogue
#pragma unroll
    for (int ni = 0; ni < 8; ni++){
        int col = nt*128 + wn*64 + ni*8 + (lid & 3)*2;
        float av0 = 0.f, av1 = 0.f;
        if (MODE == 1){
            av0 = addvec[(size_t)id*DIM + col];
            av1 = addvec[(size_t)id*DIM + col + 1];
        }
#pragma unroll
        for (int mi = 0; mi < 4; mi++){
#pragma unroll
            for (int h = 0; h < 2; h++){
                int gm = mt*128 + wm*64 + mi*16 + (lid >> 2) + h*8;
                float v0 = acc[mi][ni][h*2]   + av0;
                float v1 = acc[mi][ni][h*2+1] + av1;
                if (MODE == 0){
                    size_t o = ((size_t)zb << 20) + (size_t)gm*DIM + col;
                    uint32_t hv = (uint32_t)__half_as_ushort(__float2half_rn(v0))
                                | ((uint32_t)__half_as_ushort(__float2half_rn(v1)) << 16);
                    *reinterpret_cast<uint32_t*>(&g_Bc[o]) = hv;
                } else {
                    size_t o = ((size_t)gm*BZ + zb)*DIM + col;
                    float2 f2; f2.x = v0; f2.y = v1;
                    *reinterpret_cast<float2*>(&out[o]) = f2;
                }
            }
        }
    }
}

extern "C" void kernel_launch(void* const* d_in, const int* in_sizes, int n_in,
                              void* d_out, int out_size) {
    const float* x      = (const float*)d_in[0];
    const int*   lids   = (const int*)d_in[1];
    const float* W_base = (const float*)d_in[2];
    const float* b_base = (const float*)d_in[3];
    const float* W      = (const float*)d_in[4];
    const float* bias   = (const float*)d_in[5];
    const int*   dlen   = (n_in > 6) ? (const int*)d_in[6] : nullptr;
    int has_dict = (n_in > 6) ? 1 : 0;
    float* out = (float*)d_out;

    cudaFuncSetAttribute(gemm_kernel<0>, cudaFuncAttributeMaxDynamicSharedMemorySize, SMEM_G);
    cudaFuncSetAttribute(gemm_kernel<1>, cudaFuncAttributeMaxDynamicSharedMemorySize, SMEM_G);

    __half *Xh, *Wt, *Wbt, *Bc;
    float* bc;
    cudaGetSymbolAddress((void**)&Xh,  g_Xh);
    cudaGetSymbolAddress((void**)&Wt,  g_Wt);
    cudaGetSymbolAddress((void**)&Wbt, g_Wbt);
    cudaGetSymbolAddress((void**)&Bc,  g_Bc);
    cudaGetSymbolAddress((void**)&bc,  g_bc);

    // One-time resource setup (handles only; captured node sequence identical per call)
    static cudaStream_t s_side = nullptr;
    static cudaEvent_t ev_tp = nullptr, ev_join = nullptr;
    if (!s_side){
        cudaStreamCreateWithFlags(&s_side, cudaStreamNonBlocking);
        cudaEventCreateWithFlags(&ev_tp, cudaEventDisableTiming);
        cudaEventCreateWithFlags(&ev_join, cudaEventDisableTiming);
    }

    // Phase 1 (alone, full DRAM bandwidth): merged transposes (W planes 0..15, W_base plane 16).
    {
        dim3 g(32, 32, 17), b(32, 8);
        transpose_half_kernel<<<g, b>>>(W, W_base, lids, dlen, has_dict);
    }
    cudaEventRecord(ev_tp, 0);

    // Phase 2: gemm0 (compute-bound) on stream 0, overlapped with the
    // memory-bound side path (split_x + bc) on the side stream.
    cudaStreamWaitEvent(s_side, ev_tp, 0);
    split_x_kernel<<<(size_t)MROWS*DIM/4/256, 256, 0, s_side>>>(x);
    bc_kernel<<<dim3(16, 8), 1024, 0, s_side>>>(W, b_base, bias, lids, dlen, has_dict);
    cudaEventRecord(ev_join, s_side);

    {
        dim3 g(8, 8, 16), b(128);
        gemm_kernel<0><<<g, b, SMEM_G>>>(Wt, Wbt, nullptr,
                                         lids, dlen, has_dict, nullptr);
    }

    // Join, then main GEMM
    cudaStreamWaitEvent(0, ev_join, 0);
    {
        dim3 g(8, 16, 16), b(128);
        gemm_kernel<1><<<g, b, SMEM_G>>>(Xh, Bc, bc,
                                         lids, dlen, has_dict, out);
    }
}

// round 17
// speedup vs baseline: 1.0431x; 1.0431x over previous
#include <cuda_runtime.h>
#include <cuda_fp16.h>
#include <cstdint>
#include <cstddef>

#define SEQ 2048
#define BZ 16
#define DIM 1024
#define MROWS (SEQ*BZ)
#define KC 32
#define NKC 32
#define TILEA 8192            // 128 rows x 32 cols fp16
#define SMEM_G (3*2*TILEA)    // 48 KB

__device__ __align__(256) __half g_Xh[(size_t)MROWS*DIM];           // fp16(x), [b][s][d]
__device__ __align__(256) __half g_Wt[(size_t)16*DIM*DIM];          // fp16(W[l]^T) : [l][e'][e]
__device__ __align__(256) __half g_Wbt[(size_t)DIM*DIM];            // fp16(W_base^T) : [d][e]
__device__ __align__(256) __half g_Bc[(size_t)16*DIM*DIM];          // fp16(Bt[l][e'][d])
__device__ __align__(256) float g_bc[16*DIM];

__device__ __forceinline__ uint32_t smem_u32(const void* p){
    uint32_t a;
    asm("{ .reg .u64 t; cvta.to.shared.u64 t, %1; cvt.u32.u64 %0, t; }" : "=r"(a) : "l"(p));
    return a;
}
#define SWZ64(o) ((o) ^ (((o) >> 3) & 0x30))

__device__ __forceinline__ void cp_async16(uint32_t s, const void* g){
    asm volatile("cp.async.cg.shared.global [%0], [%1], 16;" :: "r"(s), "l"(g));
}
#define CP_COMMIT() asm volatile("cp.async.commit_group;" ::: "memory")
#define CP_WAIT1()  asm volatile("cp.async.wait_group 1;" ::: "memory")
#define CP_WAIT0()  asm volatile("cp.async.wait_group 0;" ::: "memory")

__device__ __forceinline__ void ldsm4(uint32_t* r, uint32_t addr){
    asm volatile("ldmatrix.sync.aligned.m8n8.x4.shared.b16 {%0,%1,%2,%3}, [%4];"
        : "=r"(r[0]), "=r"(r[1]), "=r"(r[2]), "=r"(r[3]) : "r"(addr));
}
__device__ __forceinline__ void mma16816h(float* d, const uint32_t* a, const uint32_t* b){
    asm volatile("mma.sync.aligned.m16n8k16.row.col.f32.f16.f16.f32 "
        "{%0,%1,%2,%3}, {%4,%5,%6,%7}, {%8,%9}, {%0,%1,%2,%3};"
        : "+f"(d[0]), "+f"(d[1]), "+f"(d[2]), "+f"(d[3])
        : "r"(a[0]), "r"(a[1]), "r"(a[2]), "r"(a[3]), "r"(b[0]), "r"(b[1]));
}

__device__ __forceinline__ bool lang_used(int l, const int* lang_ids, const int* dict_len, int has_dict){
    int dl = has_dict ? dict_len[0] : 32000;
    bool u = false;
#pragma unroll
    for (int i = 0; i < BZ; i++) u |= ((dl - 1 - lang_ids[i]) == l);
    return u;
}

// ---------------- prologue kernels ----------------
// x[s][b][d] fp32 -> Xh[b][s][d] fp16 (batch-major so gemm1 A tiles are contiguous)
__global__ void split_x_kernel(const float* __restrict__ in){
    size_t i = (size_t)blockIdx.x * 256 + threadIdx.x;   // i indexes float4 groups
    float4 v = reinterpret_cast<const float4*>(in)[i];
    uint32_t h[4];
    float f[4] = {v.x, v.y, v.z, v.w};
#pragma unroll
    for (int k = 0; k < 4; k++)
        h[k] = (uint32_t)__half_as_ushort(__float2half_rn(f[k]));
    uint2 ph; ph.x = h[0] | (h[1] << 16); ph.y = h[2] | (h[3] << 16);
    size_t row = i >> 8;                 // (s*BZ + b), 256 float4 per row
    size_t s = row >> 4, b = row & 15;
    size_t drow = (b << 11) + s;         // b*SEQ + s
    reinterpret_cast<uint2*>(g_Xh)[(drow << 8) + (i & 255)] = ph;
}
// Merged transpose, 64x64 tiles, half2 stores (128B store transactions).
// planes 0..15: W[l] -> g_Wt[l] (lang-skipped); plane 16: W_base -> g_Wbt.
__global__ void __launch_bounds__(256) transpose_half_kernel(
    const float* __restrict__ W, const float* __restrict__ W_base,
    const int* __restrict__ lang_ids, const int* __restrict__ dict_len, int has_dict){
    int l = blockIdx.z;
    const float* src;
    __half* dst;
    if (l < 16){
        if (!lang_used(l, lang_ids, dict_len, has_dict)) return;
        src = W + ((size_t)l << 20);
        dst = g_Wt + ((size_t)l << 20);
    } else {
        src = W_base;
        dst = g_Wbt;
    }
    __shared__ float ts[64][65];
    int r0 = blockIdx.x * 64;
    int c0 = blockIdx.y * 64;
    int tx = threadIdx.x & 31, ty = threadIdx.x >> 5;   // 32 x 8
    // load: warp reads 128B rows
#pragma unroll
    for (int j = 0; j < 8; j++){
        int row = ty + 8*j;
        const float* s0 = src + (size_t)(r0 + row) * DIM + c0;
        ts[row][tx]      = s0[tx];
        ts[row][tx + 32] = s0[tx + 32];
    }
    __syncthreads();
    // store: warp writes one output row (c fixed), 32 lanes x half2 = 128B
#pragma unroll
    for (int jc = 0; jc < 8; jc++){
        int c = ty + 8*jc;
        __half2 hv;
        hv.x = __float2half_rn(ts[2*tx][c]);
        hv.y = __float2half_rn(ts[2*tx + 1][c]);
        *reinterpret_cast<__half2*>(&dst[(size_t)(c0 + c) * DIM + r0 + 2*tx]) = hv;
    }
}
// bc[l][e'] = bias[l][e'] + sum_e b_base[e] * W[l][e][e']   (parallel e-reduction)
__global__ void __launch_bounds__(1024,1) bc_kernel(
    const float* __restrict__ W, const float* __restrict__ b_base,
    const float* __restrict__ bias,
    const int* __restrict__ lang_ids, const int* __restrict__ dict_len, int has_dict){
    int l = blockIdx.x;
    if (!lang_used(l, lang_ids, dict_len, has_dict)) return;
    __shared__ float red[1024];
    int t  = threadIdx.x & 127;
    int es = threadIdx.x >> 7;
    int e2 = blockIdx.y * 128 + t;
    const float* Wl = W + ((size_t)l << 20);
    float s = 0.f;
#pragma unroll 8
    for (int e = es*128; e < es*128 + 128; e++)
        s += b_base[e] * Wl[(size_t)e * DIM + e2];
    red[threadIdx.x] = s;
    __syncthreads();
#pragma unroll
    for (int st = 512; st >= 128; st >>= 1){
        if (threadIdx.x < st) red[threadIdx.x] += red[threadIdx.x + st];
        __syncthreads();
    }
    if (threadIdx.x < 128)
        g_bc[l * DIM + e2] = red[threadIdx.x] + bias[(size_t)l * DIM + e2];
}

// ---------------- GEMM via mma.sync fp16, fully 1-pass (R8 config) ----------------
// CTA tile 128x128, warp tile 64x64 (2x2), K-chunk 32, SW64, 3 stages, 128 threads, 2 CTA/SM.
// MODE 0: Bt[l] = Wt[l] @ Wbt^T -> g_Bc fp16 (skips unused l)
// MODE 1: out[s][bb][e'] = Xh[bb][s][:] @ Bt[id]^T + bc[id]
template<int MODE>
__global__ void __launch_bounds__(128,2) gemm_kernel(
    const __half* __restrict__ A0, const __half* __restrict__ B0,
    const float* __restrict__ addvec,
    const int* __restrict__ lang_ids, const int* __restrict__ dict_len, int has_dict,
    float* __restrict__ out)
{
    extern __shared__ char smem_raw[];
    uint32_t tiles = smem_u32(smem_raw);
    int tid = threadIdx.x, wid = tid >> 5, lid = tid & 31;
    int wm = wid & 1, wn = wid >> 1;
    int nt = blockIdx.x, mt = blockIdx.y, zb = blockIdx.z;

    const __half *Asrc, *Bsrc;
    int id = 0;
    if (MODE == 0){
        if (!lang_used(zb, lang_ids, dict_len, has_dict)) return;
        Asrc = A0 + ((size_t)zb << 20) + (size_t)mt*128*DIM;
        Bsrc = B0 + (size_t)nt*128*DIM;
    } else {
        int dl = has_dict ? dict_len[0] : 32000;
        id = dl - 1 - lang_ids[zb];
        Asrc = A0 + ((size_t)zb*SEQ + (size_t)mt*128)*DIM;     // [b][s][d] contiguous
        Bsrc = B0 + ((size_t)id << 20) + (size_t)nt*128*DIM;
    }

    auto load_stage = [&](int kc, int st){
        uint32_t sb = tiles + st * (2*TILEA);
        const char* gA = (const char*)Asrc + (size_t)kc * (KC*2);
        const char* gB = (const char*)Bsrc + (size_t)kc * (KC*2);
#pragma unroll
        for (int i = 0; i < 4; i++){
            int idx = tid + 128 * i;
            int row = idx >> 2, seg = idx & 3;
            uint32_t so = SWZ64(row*64 + seg*16);
            cp_async16(sb + so, gA + (size_t)row*2048 + seg*16);
            cp_async16(sb + TILEA + so, gB + (size_t)row*2048 + seg*16);
        }
        CP_COMMIT();
    };

    float acc[4][8][4];
#pragma unroll
    for (int a = 0; a < 4; a++)
#pragma unroll
        for (int b = 0; b < 8; b++)
#pragma unroll
            for (int c = 0; c < 4; c++) acc[a][b][c] = 0.f;

    int a_row = wm*64 + (lid & 7) + ((lid >> 3) & 1) * 8;
    int a_sg  = (lid >> 4);
    int b_row = wn*64 + (lid & 7) + (lid >> 4) * 8;
    int b_sg  = (lid >> 3) & 1;

    load_stage(0, 0); load_stage(1, 1);

    for (int kc = 0; kc < NKC; kc++){
        int st = kc % 3;
        if (kc == NKC-1) { CP_WAIT0(); } else { CP_WAIT1(); }
        __syncthreads();
        if (kc + 2 < NKC) load_stage(kc + 2, (kc + 2) % 3);

        uint32_t sb = tiles + st * (2*TILEA);
        uint32_t sA = sb, sB = sb + TILEA;
#pragma unroll
        for (int ks = 0; ks < 2; ks++){
            uint32_t ah[4][4], bh[4][4];
#pragma unroll
            for (int mi = 0; mi < 4; mi++){
                uint32_t off = SWZ64((a_row + mi*16)*64 + (ks*2 + a_sg)*16);
                ldsm4(ah[mi], sA + off);
            }
#pragma unroll
            for (int ni2 = 0; ni2 < 4; ni2++){
                uint32_t off = SWZ64((b_row + ni2*16)*64 + (ks*2 + b_sg)*16);
                ldsm4(bh[ni2], sB + off);
            }
#pragma unroll
            for (int mi = 0; mi < 4; mi++)
#pragma unroll
                for (int ni = 0; ni < 8; ni++)
                    mma16816h(acc[mi][ni], ah[mi], &bh[ni>>1][(ni&1)*2]);
        }
    }

    // epilogue
#pragma unroll
    for (int ni = 0; ni < 8; ni++){
        int col = nt*128 + wn*64 + ni*8 + (lid & 3)*2;
        float av0 = 0.f, av1 = 0.f;
        if (MODE == 1){
            av0 = addvec[(size_t)id*DIM + col];
            av1 = addvec[(size_t)id*DIM + col + 1];
        }
#pragma unroll
        for (int mi = 0; mi < 4; mi++){
#pragma unroll
            for (int h = 0; h < 2; h++){
                int gm = mt*128 + wm*64 + mi*16 + (lid >> 2) + h*8;
                float v0 = acc[mi][ni][h*2]   + av0;
                float v1 = acc[mi][ni][h*2+1] + av1;
                if (MODE == 0){
                    size_t o = ((size_t)zb << 20) + (size_t)gm*DIM + col;
                    uint32_t hv = (uint32_t)__half_as_ushort(__float2half_rn(v0))
                                | ((uint32_t)__half_as_ushort(__float2half_rn(v1)) << 16);
                    *reinterpret_cast<uint32_t*>(&g_Bc[o]) = hv;
                } else {
                    size_t o = ((size_t)gm*BZ + zb)*DIM + col;
                    float2 f2; f2.x = v0; f2.y = v1;
                    *reinterpret_cast<float2*>(&out[o]) = f2;
                }
            }
        }
    }
}

extern "C" void kernel_launch(void* const* d_in, const int* in_sizes, int n_in,
                              void* d_out, int out_size) {
    const float* x      = (const float*)d_in[0];
    const int*   lids   = (const int*)d_in[1];
    const float* W_base = (const float*)d_in[2];
    const float* b_base = (const float*)d_in[3];
    const float* W      = (const float*)d_in[4];
    const float* bias   = (const float*)d_in[5];
    const int*   dlen   = (n_in > 6) ? (const int*)d_in[6] : nullptr;
    int has_dict = (n_in > 6) ? 1 : 0;
    float* out = (float*)d_out;

    cudaFuncSetAttribute(gemm_kernel<0>, cudaFuncAttributeMaxDynamicSharedMemorySize, SMEM_G);
    cudaFuncSetAttribute(gemm_kernel<1>, cudaFuncAttributeMaxDynamicSharedMemorySize, SMEM_G);

    __half *Xh, *Wt, *Wbt, *Bc;
    float* bc;
    cudaGetSymbolAddress((void**)&Xh,  g_Xh);
    cudaGetSymbolAddress((void**)&Wt,  g_Wt);
    cudaGetSymbolAddress((void**)&Wbt, g_Wbt);
    cudaGetSymbolAddress((void**)&Bc,  g_Bc);
    cudaGetSymbolAddress((void**)&bc,  g_bc);

    // One-time resource setup (handles only; captured node sequence identical per call)
    static cudaStream_t s_side = nullptr;
    static cudaEvent_t ev_fork = nullptr, ev_join = nullptr;
    if (!s_side){
        cudaStreamCreateWithFlags(&s_side, cudaStreamNonBlocking);
        cudaEventCreateWithFlags(&ev_fork, cudaEventDisableTiming);
        cudaEventCreateWithFlags(&ev_join, cudaEventDisableTiming);
    }

    // Fork (R14 graph): side path (split_x + bc) concurrent with transpose+gemm0.
    cudaEventRecord(ev_fork, 0);
    cudaStreamWaitEvent(s_side, ev_fork, 0);

    split_x_kernel<<<(size_t)MROWS*DIM/4/256, 256, 0, s_side>>>(x);
    bc_kernel<<<dim3(16, 8), 1024, 0, s_side>>>(W, b_base, bias, lids, dlen, has_dict);
    cudaEventRecord(ev_join, s_side);

    // Main path: merged transposes (W planes 0..15, W_base plane 16) -> gemm0
    {
        dim3 g(16, 16, 17), b(256);
        transpose_half_kernel<<<g, b>>>(W, W_base, lids, dlen, has_dict);
    }
    {
        dim3 g(8, 8, 16), b(128);
        gemm_kernel<0><<<g, b, SMEM_G>>>(Wt, Wbt, nullptr,
                                         lids, dlen, has_dict, nullptr);
    }

    // Join, then main GEMM
    cudaStreamWaitEvent(0, ev_join, 0);
    {
        dim3 g(8, 16, 16), b(128);
        gemm_kernel<1><<<g, b, SMEM_G>>>(Xh, Bc, bc,
                                         lids, dlen, has_dict, out);
    }
}